// round 1
// baseline (speedup 1.0000x reference)
#include <cuda_runtime.h>
#include <cuda_bf16.h>
#include <math.h>

#define S 1024
#define H 2048
#define NH 16
#define HD 128
#define E 8
#define FI 1408
#define SFI 2816

// ---------------- scratch (device globals: allocation-free) ----------------
__device__ float g_h1[S * H];
__device__ float g_q[S * H];
__device__ float g_k[S * H];
__device__ float g_vt[H * S];            // transposed V: [H][S]
__device__ float g_scores[(size_t)NH * S * S];
__device__ float g_attn[S * H];
__device__ float g_x[S * H];
__device__ float g_h2[S * H];
__device__ float g_eg[(size_t)E * S * FI];
__device__ float g_eu[(size_t)E * S * FI];
__device__ float g_routed[2ul * S * H];  // two top-k rank slots
__device__ float g_sg[(size_t)S * SFI];
__device__ float g_su[(size_t)S * SFI];
__device__ float g_sd[S * H];
__device__ int   g_counts[E];
__device__ int   g_tok[E * S];
__device__ float g_tw[E * S];
__device__ int   g_rank[E * S];
__device__ float g_invfreq[64];

// ---------------- helpers ----------------
__device__ __forceinline__ float cvt_tf32(float x) {
    float r;
    asm("cvt.rna.tf32.f32 %0, %1;" : "=f"(r) : "f"(x));
    return r;
}

__device__ __forceinline__ float blockReduceSum(float v) {
    __shared__ float sm[8];
    for (int o = 16; o; o >>= 1) v += __shfl_xor_sync(0xffffffffu, v, o);
    if ((threadIdx.x & 31) == 0) sm[threadIdx.x >> 5] = v;
    __syncthreads();
    float r = sm[0];
#pragma unroll
    for (int i = 1; i < 8; i++) r += sm[i];
    __syncthreads();
    return r;
}

__device__ __forceinline__ float blockReduceMax(float v) {
    __shared__ float sm[8];
    for (int o = 16; o; o >>= 1) v = fmaxf(v, __shfl_xor_sync(0xffffffffu, v, o));
    if ((threadIdx.x & 31) == 0) sm[threadIdx.x >> 5] = v;
    __syncthreads();
    float r = sm[0];
#pragma unroll
    for (int i = 1; i < 8; i++) r = fmaxf(r, sm[i]);
    __syncthreads();
    return r;
}

// ---------------- generic TF32 GEMM: C[M,N] = scale * A[M,K] * B[N,K]^T ----------------
// flags: 1 = gather A rows via tok list, 2 = scatter epilogue (routed MoE),
//        4 = causal tile skip, 8 = transposed C store
__global__ void __launch_bounds__(256) gemm_tf32(
    const float* __restrict__ A, int lda, long sAz,
    const float* __restrict__ B, int ldb, long sBz,
    float* __restrict__ C, int ldc, long sCz,
    int M, int N, int K, float scale,
    const float* __restrict__ addsrc,
    const int* __restrict__ counts,
    const int* __restrict__ tok,
    const float* __restrict__ tw,
    const int* __restrict__ rnk,
    float* __restrict__ scat, long scatStride,
    int flags)
{
    const int z  = blockIdx.z;
    const int m0 = blockIdx.y * 128;
    const int n0 = blockIdx.x * 128;
    const int Meff = counts ? counts[z] : M;
    if (m0 >= Meff) return;
    if ((flags & 4) && n0 >= m0 + 128) return;   // fully-masked causal tile

    A += sAz * z; B += sBz * z; C += sCz * z;
    const int* tokz = tok ? tok + z * S : nullptr;

    __shared__ float sA[128][36];
    __shared__ float sB[128][36];

    const int tid = threadIdx.x;
    const int lane = tid & 31, warp = tid >> 5;
    const int wm = (warp >> 2) * 64, wn = (warp & 3) * 32;
    const int g = lane >> 2, t = lane & 3;

    const int lr = tid >> 3;
    const int lc = (tid & 7) * 4;

    const float* aPtr[4];
    bool aOk[4];
    const float* bPtr[4];
#pragma unroll
    for (int j = 0; j < 4; j++) {
        int m = m0 + lr + 32 * j;
        bool ok = m < Meff;
        int rr = m;
        if ((flags & 1) && ok) rr = tokz[m];
        aPtr[j] = A + (long)rr * lda + lc;
        aOk[j] = ok;
        int n = n0 + lr + 32 * j;
        bPtr[j] = B + (long)n * ldb + lc;
    }

    float acc[4][4][4];
#pragma unroll
    for (int a = 0; a < 4; a++)
#pragma unroll
        for (int b = 0; b < 4; b++)
#pragma unroll
            for (int c = 0; c < 4; c++) acc[a][b][c] = 0.f;

    for (int k0 = 0; k0 < K; k0 += 32) {
#pragma unroll
        for (int j = 0; j < 4; j++) {
            float4 va = aOk[j] ? *(const float4*)(aPtr[j] + k0) : make_float4(0.f, 0.f, 0.f, 0.f);
            va.x = cvt_tf32(va.x); va.y = cvt_tf32(va.y);
            va.z = cvt_tf32(va.z); va.w = cvt_tf32(va.w);
            *(float4*)&sA[lr + 32 * j][lc] = va;
            float4 vb = *(const float4*)(bPtr[j] + k0);
            vb.x = cvt_tf32(vb.x); vb.y = cvt_tf32(vb.y);
            vb.z = cvt_tf32(vb.z); vb.w = cvt_tf32(vb.w);
            *(float4*)&sB[lr + 32 * j][lc] = vb;
        }
        __syncthreads();
#pragma unroll
        for (int kk = 0; kk < 32; kk += 8) {
            unsigned af[4][4], bf[4][2];
#pragma unroll
            for (int mi = 0; mi < 4; mi++) {
                int r = wm + mi * 16;
                af[mi][0] = __float_as_uint(sA[r + g    ][kk + t    ]);
                af[mi][1] = __float_as_uint(sA[r + g + 8][kk + t    ]);
                af[mi][2] = __float_as_uint(sA[r + g    ][kk + t + 4]);
                af[mi][3] = __float_as_uint(sA[r + g + 8][kk + t + 4]);
            }
#pragma unroll
            for (int ni = 0; ni < 4; ni++) {
                int c = wn + ni * 8;
                bf[ni][0] = __float_as_uint(sB[c + g][kk + t    ]);
                bf[ni][1] = __float_as_uint(sB[c + g][kk + t + 4]);
            }
#pragma unroll
            for (int mi = 0; mi < 4; mi++)
#pragma unroll
                for (int ni = 0; ni < 4; ni++)
                    asm volatile(
                        "mma.sync.aligned.m16n8k8.row.col.f32.tf32.tf32.f32 "
                        "{%0,%1,%2,%3}, {%4,%5,%6,%7}, {%8,%9}, {%0,%1,%2,%3};"
                        : "+f"(acc[mi][ni][0]), "+f"(acc[mi][ni][1]),
                          "+f"(acc[mi][ni][2]), "+f"(acc[mi][ni][3])
                        : "r"(af[mi][0]), "r"(af[mi][1]), "r"(af[mi][2]), "r"(af[mi][3]),
                          "r"(bf[ni][0]), "r"(bf[ni][1]));
        }
        __syncthreads();
    }

    // epilogue: c0=(g,2t) c1=(g,2t+1) c2=(g+8,2t) c3=(g+8,2t+1)
#pragma unroll
    for (int mi = 0; mi < 4; mi++) {
#pragma unroll
        for (int ni = 0; ni < 4; ni++) {
            int r0 = m0 + wm + mi * 16 + g;
            int c0 = n0 + wn + ni * 8 + t * 2;
#pragma unroll
            for (int hh = 0; hh < 2; hh++) {
                int r = r0 + hh * 8;
                if (r >= Meff) continue;
                float v0 = acc[mi][ni][hh * 2 + 0] * scale;
                float v1 = acc[mi][ni][hh * 2 + 1] * scale;
                if (flags & 2) {
                    int rr = tokz[r];
                    float w = tw[z * S + r];
                    float* dst = scat + (long)rnk[z * S + r] * scatStride + (long)rr * ldc + c0;
                    dst[0] = w * v0;
                    dst[1] = w * v1;
                } else if (flags & 8) {
                    C[(long)c0 * ldc + r] = v0;
                    C[(long)(c0 + 1) * ldc + r] = v1;
                } else {
                    long o = (long)r * ldc + c0;
                    if (addsrc) { v0 += addsrc[o]; v1 += addsrc[o + 1]; }
                    C[o] = v0;
                    C[o + 1] = v1;
                }
            }
        }
    }
}

// ---------------- small kernels ----------------
__global__ void init_misc() {
    int i = threadIdx.x;
    if (i < 64) g_invfreq[i] = (float)pow(10000.0, -(double)i / 64.0);
    if (i < E)  g_counts[i] = 0;
}

__global__ void rmsnorm_kernel(const float* __restrict__ x, const float* __restrict__ w,
                               float* __restrict__ o) {
    long r = blockIdx.x;
    const float* xr = x + r * H;
    float s = 0.f;
    for (int i = threadIdx.x; i < H; i += 256) { float v = xr[i]; s += v * v; }
    s = blockReduceSum(s);
    float inv = rsqrtf(s / (float)H + 1e-6f);
    for (int i = threadIdx.x; i < H; i += 256) o[r * H + i] = xr[i] * inv * w[i];
}

__global__ void rope_kernel() {
    int s = blockIdx.x;
    for (int p = threadIdx.x; p < NH * 64; p += blockDim.x) {
        int head = p >> 6, i = p & 63;
        float f = (float)s * g_invfreq[i];
        float sn, cs;
        sincosf(f, &sn, &cs);
        long b = (long)s * H + head * HD;
        float q1 = g_q[b + i], q2 = g_q[b + i + 64];
        g_q[b + i]      = q1 * cs - q2 * sn;
        g_q[b + i + 64] = q2 * cs + q1 * sn;
        float k1 = g_k[b + i], k2 = g_k[b + i + 64];
        g_k[b + i]      = k1 * cs - k2 * sn;
        g_k[b + i + 64] = k2 * cs + k1 * sn;
    }
}

__global__ void softmax_causal(float* __restrict__ sc) {
    int h = blockIdx.y, r = blockIdx.x;
    float* row = sc + ((long)h * S + r) * S;
    float mx = -3.4e38f;
    for (int c = threadIdx.x; c <= r; c += 256) mx = fmaxf(mx, row[c]);
    mx = blockReduceMax(mx);
    float sum = 0.f;
    for (int c = threadIdx.x; c <= r; c += 256) {
        float e = expf(row[c] - mx);
        row[c] = e;
        sum += e;
    }
    sum = blockReduceSum(sum);
    float inv = 1.f / sum;
    for (int c = threadIdx.x; c <= r; c += 256) row[c] *= inv;
    for (int c = r + 1 + threadIdx.x; c < S; c += 256) row[c] = 0.f;
}

__global__ void gate_topk(const float* __restrict__ h2, const float* __restrict__ gw) {
    int n = blockIdx.x;
    int warp = threadIdx.x >> 5, lane = threadIdx.x & 31;
    __shared__ float lg[E];
    const float* x = h2 + (long)n * H;
    const float* w = gw + (long)warp * H;
    float p = 0.f;
    for (int i = lane; i < H; i += 32) p += x[i] * w[i];
    for (int o = 16; o; o >>= 1) p += __shfl_xor_sync(0xffffffffu, p, o);
    if (lane == 0) lg[warp] = p;
    __syncthreads();
    if (threadIdx.x == 0) {
        float mx = lg[0];
        for (int e = 1; e < E; e++) mx = fmaxf(mx, lg[e]);
        float pe[E], s = 0.f;
        for (int e = 0; e < E; e++) { pe[e] = expf(lg[e] - mx); s += pe[e]; }
        float inv = 1.f / s;
        for (int e = 0; e < E; e++) pe[e] *= inv;
        int i1 = 0;
        for (int e = 1; e < E; e++) if (pe[e] > pe[i1]) i1 = e;
        int i2 = (i1 == 0) ? 1 : 0;
        for (int e = 0; e < E; e++) if (e != i1 && pe[e] > pe[i2]) i2 = e;
        float w1 = pe[i1], w2 = pe[i2];
        float wi = 1.f / (w1 + w2 + 1e-20f);
        w1 *= wi; w2 *= wi;
        int s1 = atomicAdd(&g_counts[i1], 1);
        g_tok[i1 * S + s1] = n; g_tw[i1 * S + s1] = w1; g_rank[i1 * S + s1] = 0;
        int s2 = atomicAdd(&g_counts[i2], 1);
        g_tok[i2 * S + s2] = n; g_tw[i2 * S + s2] = w2; g_rank[i2 * S + s2] = 1;
    }
}

__global__ void silu_expert() {
    int e = blockIdx.y;
    long total = (long)g_counts[e] * FI;
    float* gb = g_eg + (long)e * S * FI;
    const float* ub = g_eu + (long)e * S * FI;
    for (long i = (long)blockIdx.x * blockDim.x + threadIdx.x; i < total;
         i += (long)gridDim.x * blockDim.x) {
        float gv = gb[i];
        gb[i] = gv / (1.f + expf(-gv)) * ub[i];
    }
}

__global__ void silu_shared() {
    long total = (long)S * SFI;
    for (long i = (long)blockIdx.x * blockDim.x + threadIdx.x; i < total;
         i += (long)gridDim.x * blockDim.x) {
        float gv = g_sg[i];
        g_sg[i] = gv / (1.f + expf(-gv)) * g_su[i];
    }
}

__global__ void final_add(float* __restrict__ out) {
    long i = (long)blockIdx.x * blockDim.x + threadIdx.x;
    out[i] = g_x[i] + g_routed[i] + g_routed[(long)S * H + i] + g_sd[i];
}

// ---------------- launch ----------------
extern "C" void kernel_launch(void* const* d_in, const int* in_sizes, int n_in,
                              void* d_out, int out_size) {
    const float* hs  = (const float*)d_in[0];
    const float* ln1 = (const float*)d_in[1];
    const float* ln2 = (const float*)d_in[2];
    const float* wq  = (const float*)d_in[3];
    const float* wk  = (const float*)d_in[4];
    const float* wv  = (const float*)d_in[5];
    const float* wo  = (const float*)d_in[6];
    const float* gw  = (const float*)d_in[7];
    const float* eg  = (const float*)d_in[8];
    const float* eu  = (const float*)d_in[9];
    const float* ed  = (const float*)d_in[10];
    const float* sgw = (const float*)d_in[11];
    const float* suw = (const float*)d_in[12];
    const float* sdw = (const float*)d_in[13];
    float* out = (float*)d_out;

    float *p_h1, *p_q, *p_k, *p_vt, *p_scores, *p_attn, *p_x, *p_h2;
    float *p_eg, *p_eu, *p_routed, *p_sg, *p_su, *p_sd, *p_tw;
    int *p_counts, *p_tok, *p_rank;
    cudaGetSymbolAddress((void**)&p_h1, g_h1);
    cudaGetSymbolAddress((void**)&p_q, g_q);
    cudaGetSymbolAddress((void**)&p_k, g_k);
    cudaGetSymbolAddress((void**)&p_vt, g_vt);
    cudaGetSymbolAddress((void**)&p_scores, g_scores);
    cudaGetSymbolAddress((void**)&p_attn, g_attn);
    cudaGetSymbolAddress((void**)&p_x, g_x);
    cudaGetSymbolAddress((void**)&p_h2, g_h2);
    cudaGetSymbolAddress((void**)&p_eg, g_eg);
    cudaGetSymbolAddress((void**)&p_eu, g_eu);
    cudaGetSymbolAddress((void**)&p_routed, g_routed);
    cudaGetSymbolAddress((void**)&p_sg, g_sg);
    cudaGetSymbolAddress((void**)&p_su, g_su);
    cudaGetSymbolAddress((void**)&p_sd, g_sd);
    cudaGetSymbolAddress((void**)&p_tw, g_tw);
    cudaGetSymbolAddress((void**)&p_counts, g_counts);
    cudaGetSymbolAddress((void**)&p_tok, g_tok);
    cudaGetSymbolAddress((void**)&p_rank, g_rank);

    init_misc<<<1, 64>>>();
    rmsnorm_kernel<<<S, 256>>>(hs, ln1, p_h1);

    dim3 gqkv(16, 8, 1);
    gemm_tf32<<<gqkv, 256>>>(p_h1, H, 0, wq, H, 0, p_q, H, 0, S, H, H, 1.f,
                             nullptr, nullptr, nullptr, nullptr, nullptr, nullptr, 0, 0);
    gemm_tf32<<<gqkv, 256>>>(p_h1, H, 0, wk, H, 0, p_k, H, 0, S, H, H, 1.f,
                             nullptr, nullptr, nullptr, nullptr, nullptr, nullptr, 0, 0);
    // V projection with transposed store -> g_vt[H][S]
    gemm_tf32<<<gqkv, 256>>>(p_h1, H, 0, wv, H, 0, p_vt, S, 0, S, H, H, 1.f,
                             nullptr, nullptr, nullptr, nullptr, nullptr, nullptr, 0, 8);

    rope_kernel<<<S, 256>>>();

    // scores = Q K^T / sqrt(HD), causal tile skip
    dim3 gsc(8, 8, NH);
    gemm_tf32<<<gsc, 256>>>(p_q, H, (long)HD, p_k, H, (long)HD,
                            p_scores, S, (long)S * S, S, S, HD, 0.08838834764831845f,
                            nullptr, nullptr, nullptr, nullptr, nullptr, nullptr, 0, 4);

    dim3 gsm(S, NH);
    softmax_causal<<<gsm, 256>>>(p_scores);

    // attn = P @ V  (V transposed -> K-major B)
    dim3 gpv(1, 8, NH);
    gemm_tf32<<<gpv, 256>>>(p_scores, S, (long)S * S, p_vt, S, (long)HD * S,
                            p_attn, H, (long)HD, S, HD, S, 1.f,
                            nullptr, nullptr, nullptr, nullptr, nullptr, nullptr, 0, 0);

    // x = residual + attn @ wo^T
    gemm_tf32<<<gqkv, 256>>>(p_attn, H, 0, wo, H, 0, p_x, H, 0, S, H, H, 1.f,
                             hs, nullptr, nullptr, nullptr, nullptr, nullptr, 0, 0);

    rmsnorm_kernel<<<S, 256>>>(p_x, ln2, p_h2);
    gate_topk<<<S, 256>>>(p_h2, gw);

    // routed experts (sparse, capacity grid with early exit on counts)
    dim3 geg(11, 8, E);
    gemm_tf32<<<geg, 256>>>(p_h2, H, 0, eg, H, (long)FI * H, p_eg, FI, (long)S * FI,
                            S, FI, H, 1.f, nullptr, p_counts, p_tok, nullptr, nullptr,
                            nullptr, 0, 1);
    gemm_tf32<<<geg, 256>>>(p_h2, H, 0, eu, H, (long)FI * H, p_eu, FI, (long)S * FI,
                            S, FI, H, 1.f, nullptr, p_counts, p_tok, nullptr, nullptr,
                            nullptr, 0, 1);
    silu_expert<<<dim3(768, E), 256>>>();
    dim3 ged(16, 8, E);
    gemm_tf32<<<ged, 256>>>(p_eg, FI, (long)S * FI, ed, FI, (long)H * FI,
                            p_routed, H, 0, S, H, FI, 1.f,
                            nullptr, p_counts, p_tok, p_tw, p_rank,
                            p_routed, (long)S * H, 2);

    // shared expert
    dim3 gsg(22, 8, 1);
    gemm_tf32<<<gsg, 256>>>(p_h2, H, 0, sgw, H, 0, p_sg, SFI, 0, S, SFI, H, 1.f,
                            nullptr, nullptr, nullptr, nullptr, nullptr, nullptr, 0, 0);
    gemm_tf32<<<gsg, 256>>>(p_h2, H, 0, suw, H, 0, p_su, SFI, 0, S, SFI, H, 1.f,
                            nullptr, nullptr, nullptr, nullptr, nullptr, nullptr, 0, 0);
    silu_shared<<<1024, 256>>>();
    dim3 gsd(16, 8, 1);
    gemm_tf32<<<gsd, 256>>>(p_sg, SFI, 0, sdw, SFI, 0, p_sd, H, 0, S, H, SFI, 1.f,
                            nullptr, nullptr, nullptr, nullptr, nullptr, nullptr, 0, 0);

    final_add<<<(S * H) / 256, 256>>>(out);
}

// round 2
// speedup vs baseline: 1.3225x; 1.3225x over previous
#include <cuda_runtime.h>
#include <cuda_bf16.h>
#include <math.h>

#define S 1024
#define H 2048
#define NH 16
#define HD 128
#define E 8
#define FI 1408
#define SFI 2816

#define STAGES 3
#define SMEM_STRIDE 36                       // 32 + 4 pad floats
#define STAGE_FLOATS (128 * SMEM_STRIDE)     // per-stage per-operand
#define DYN_SMEM_BYTES (STAGES * 2 * STAGE_FLOATS * 4)

// ---------------- scratch (device globals: allocation-free) ----------------
__device__ float g_h1[S * H];
__device__ float g_q[S * H];
__device__ float g_k[S * H];
__device__ float g_vt[H * S];            // transposed V: [H][S]
__device__ float g_scores[(size_t)NH * S * S];
__device__ float g_attn[S * H];
__device__ float g_x[S * H];
__device__ float g_h2[S * H];
__device__ float g_eg[(size_t)E * S * FI];
__device__ float g_eu[(size_t)E * S * FI];
__device__ float g_routed[2ul * S * H];  // two top-k rank slots
__device__ float g_sg[(size_t)S * SFI];
__device__ float g_su[(size_t)S * SFI];
__device__ float g_sd[S * H];
__device__ int   g_counts[E];
__device__ int   g_tok[E * S];
__device__ float g_tw[E * S];
__device__ int   g_rank[E * S];
__device__ float g_invfreq[64];

// ---------------- helpers ----------------
__device__ __forceinline__ unsigned ld_tf32(const float* p) {
    float r;
    asm("cvt.rna.tf32.f32 %0, %1;" : "=f"(r) : "f"(*p));
    return __float_as_uint(r);
}

__device__ __forceinline__ void cp_async16(unsigned saddr, const void* g, bool pred) {
    int sz = pred ? 16 : 0;
    asm volatile("cp.async.cg.shared.global [%0], [%1], 16, %2;\n"
                 :: "r"(saddr), "l"(g), "r"(sz));
}

__device__ __forceinline__ float blockReduceSum(float v) {
    __shared__ float sm[8];
    for (int o = 16; o; o >>= 1) v += __shfl_xor_sync(0xffffffffu, v, o);
    if ((threadIdx.x & 31) == 0) sm[threadIdx.x >> 5] = v;
    __syncthreads();
    float r = sm[0];
#pragma unroll
    for (int i = 1; i < 8; i++) r += sm[i];
    __syncthreads();
    return r;
}

__device__ __forceinline__ float blockReduceMax(float v) {
    __shared__ float sm[8];
    for (int o = 16; o; o >>= 1) v = fmaxf(v, __shfl_xor_sync(0xffffffffu, v, o));
    if ((threadIdx.x & 31) == 0) sm[threadIdx.x >> 5] = v;
    __syncthreads();
    float r = sm[0];
#pragma unroll
    for (int i = 1; i < 8; i++) r = fmaxf(r, sm[i]);
    __syncthreads();
    return r;
}

// ---------------- generic TF32 GEMM: C[M,N] = scale * A[M,K] * B[N,K]^T ----------------
// cp.async 3-stage pipelined. flags: 1 = gather A rows via tok list,
// 2 = scatter epilogue (routed MoE), 4 = causal tile skip, 8 = transposed C store
__global__ void __launch_bounds__(256, 2) gemm_tf32(
    const float* __restrict__ A, int lda, long sAz,
    const float* __restrict__ B, int ldb, long sBz,
    float* __restrict__ C, int ldc, long sCz,
    int M, int N, int K, float scale,
    const float* __restrict__ addsrc,
    const int* __restrict__ counts,
    const int* __restrict__ tok,
    const float* __restrict__ tw,
    const int* __restrict__ rnk,
    float* __restrict__ scat, long scatStride,
    int flags)
{
    const int z  = blockIdx.z;
    const int m0 = blockIdx.y * 128;
    const int n0 = blockIdx.x * 128;
    const int Meff = counts ? counts[z] : M;
    if (m0 >= Meff) return;
    if ((flags & 4) && n0 >= m0 + 128) return;   // fully-masked causal tile

    A += sAz * z; B += sBz * z; C += sCz * z;
    const int* tokz = tok ? tok + z * S : nullptr;

    extern __shared__ float dynsmem[];
    float* sAb = dynsmem;                              // [STAGES][128][36]
    float* sBb = dynsmem + STAGES * STAGE_FLOATS;

    const int tid = threadIdx.x;
    const int lane = tid & 31, warp = tid >> 5;
    const int wm = (warp >> 2) * 64, wn = (warp & 3) * 32;
    const int g = lane >> 2, t = lane & 3;

    const int lr = tid >> 3;          // 0..31
    const int lc = (tid & 7) * 4;     // 0..28

    const float* aPtr[4];
    bool aOk[4];
    const float* bPtr[4];
#pragma unroll
    for (int j = 0; j < 4; j++) {
        int m = m0 + lr + 32 * j;
        bool ok = m < Meff;
        int rr = ok ? m : 0;
        if ((flags & 1) && ok) rr = tokz[m];
        aPtr[j] = A + (long)rr * lda + lc;
        aOk[j] = ok;
        int n = n0 + lr + 32 * j;
        bPtr[j] = B + (long)n * ldb + lc;
    }

    const unsigned stageB = STAGE_FLOATS * 4;
    unsigned saA = (unsigned)__cvta_generic_to_shared(sAb) + (lr * SMEM_STRIDE + lc) * 4;
    unsigned saB = (unsigned)__cvta_generic_to_shared(sBb) + (lr * SMEM_STRIDE + lc) * 4;

    float acc[4][4][4];
#pragma unroll
    for (int a = 0; a < 4; a++)
#pragma unroll
        for (int b = 0; b < 4; b++)
#pragma unroll
            for (int c = 0; c < 4; c++) acc[a][b][c] = 0.f;

    const int KT = K >> 5;

#define LOAD_TILE(TILE, STG)                                                        \
    {                                                                               \
        long k0_ = (long)(TILE) * 32;                                               \
        unsigned so_ = (STG) * stageB;                                              \
        _Pragma("unroll")                                                           \
        for (int j = 0; j < 4; j++) {                                               \
            cp_async16(saA + so_ + j * (32 * SMEM_STRIDE * 4), aPtr[j] + k0_, aOk[j]); \
            cp_async16(saB + so_ + j * (32 * SMEM_STRIDE * 4), bPtr[j] + k0_, true);  \
        }                                                                           \
        asm volatile("cp.async.commit_group;" ::: "memory");                        \
    }

    LOAD_TILE(0, 0)
    LOAD_TILE(1, 1)

    for (int kt = 0; kt < KT; kt++) {
        asm volatile("cp.async.wait_group 1;" ::: "memory");
        __syncthreads();

        int nt = kt + 2;
        if (nt < KT) {
            int stg = nt % STAGES;
            LOAD_TILE(nt, stg)
        } else {
            asm volatile("cp.async.commit_group;" ::: "memory");
        }

        const float* cA = sAb + (kt % STAGES) * STAGE_FLOATS;
        const float* cB = sBb + (kt % STAGES) * STAGE_FLOATS;
#pragma unroll
        for (int kk = 0; kk < 32; kk += 8) {
            unsigned af[4][4], bf[4][2];
#pragma unroll
            for (int mi = 0; mi < 4; mi++) {
                int r = wm + mi * 16;
                af[mi][0] = ld_tf32(cA + (r + g    ) * SMEM_STRIDE + kk + t    );
                af[mi][1] = ld_tf32(cA + (r + g + 8) * SMEM_STRIDE + kk + t    );
                af[mi][2] = ld_tf32(cA + (r + g    ) * SMEM_STRIDE + kk + t + 4);
                af[mi][3] = ld_tf32(cA + (r + g + 8) * SMEM_STRIDE + kk + t + 4);
            }
#pragma unroll
            for (int ni = 0; ni < 4; ni++) {
                int c = wn + ni * 8;
                bf[ni][0] = ld_tf32(cB + (c + g) * SMEM_STRIDE + kk + t    );
                bf[ni][1] = ld_tf32(cB + (c + g) * SMEM_STRIDE + kk + t + 4);
            }
#pragma unroll
            for (int mi = 0; mi < 4; mi++)
#pragma unroll
                for (int ni = 0; ni < 4; ni++)
                    asm volatile(
                        "mma.sync.aligned.m16n8k8.row.col.f32.tf32.tf32.f32 "
                        "{%0,%1,%2,%3}, {%4,%5,%6,%7}, {%8,%9}, {%0,%1,%2,%3};"
                        : "+f"(acc[mi][ni][0]), "+f"(acc[mi][ni][1]),
                          "+f"(acc[mi][ni][2]), "+f"(acc[mi][ni][3])
                        : "r"(af[mi][0]), "r"(af[mi][1]), "r"(af[mi][2]), "r"(af[mi][3]),
                          "r"(bf[ni][0]), "r"(bf[ni][1]));
        }
    }

    // epilogue: c0=(g,2t) c1=(g,2t+1) c2=(g+8,2t) c3=(g+8,2t+1)
#pragma unroll
    for (int mi = 0; mi < 4; mi++) {
#pragma unroll
        for (int ni = 0; ni < 4; ni++) {
            int r0 = m0 + wm + mi * 16 + g;
            int c0 = n0 + wn + ni * 8 + t * 2;
#pragma unroll
            for (int hh = 0; hh < 2; hh++) {
                int r = r0 + hh * 8;
                if (r >= Meff) continue;
                float v0 = acc[mi][ni][hh * 2 + 0] * scale;
                float v1 = acc[mi][ni][hh * 2 + 1] * scale;
                if (flags & 2) {
                    int rr = tokz[r];
                    float w = tw[z * S + r];
                    float* dst = scat + (long)rnk[z * S + r] * scatStride + (long)rr * ldc + c0;
                    dst[0] = w * v0;
                    dst[1] = w * v1;
                } else if (flags & 8) {
                    C[(long)c0 * ldc + r] = v0;
                    C[(long)(c0 + 1) * ldc + r] = v1;
                } else {
                    long o = (long)r * ldc + c0;
                    if (addsrc) { v0 += addsrc[o]; v1 += addsrc[o + 1]; }
                    C[o] = v0;
                    C[o + 1] = v1;
                }
            }
        }
    }
}

// ---------------- small kernels ----------------
__global__ void init_misc() {
    int i = threadIdx.x;
    if (i < 64) g_invfreq[i] = (float)pow(10000.0, -(double)i / 64.0);
    if (i < E)  g_counts[i] = 0;
}

__global__ void rmsnorm_kernel(const float* __restrict__ x, const float* __restrict__ w,
                               float* __restrict__ o) {
    long r = blockIdx.x;
    const float* xr = x + r * H;
    float s = 0.f;
    for (int i = threadIdx.x; i < H; i += 256) { float v = xr[i]; s += v * v; }
    s = blockReduceSum(s);
    float inv = rsqrtf(s / (float)H + 1e-6f);
    for (int i = threadIdx.x; i < H; i += 256) o[r * H + i] = xr[i] * inv * w[i];
}

__global__ void rope_kernel() {
    int s = blockIdx.x;
    for (int p = threadIdx.x; p < NH * 64; p += blockDim.x) {
        int head = p >> 6, i = p & 63;
        float f = (float)s * g_invfreq[i];
        float sn, cs;
        sincosf(f, &sn, &cs);
        long b = (long)s * H + head * HD;
        float q1 = g_q[b + i], q2 = g_q[b + i + 64];
        g_q[b + i]      = q1 * cs - q2 * sn;
        g_q[b + i + 64] = q2 * cs + q1 * sn;
        float k1 = g_k[b + i], k2 = g_k[b + i + 64];
        g_k[b + i]      = k1 * cs - k2 * sn;
        g_k[b + i + 64] = k2 * cs + k1 * sn;
    }
}

__global__ void softmax_causal(float* __restrict__ sc) {
    int h = blockIdx.y, r = blockIdx.x;
    float* row = sc + ((long)h * S + r) * S;
    float mx = -3.4e38f;
    for (int c = threadIdx.x; c <= r; c += 256) mx = fmaxf(mx, row[c]);
    mx = blockReduceMax(mx);
    float sum = 0.f;
    for (int c = threadIdx.x; c <= r; c += 256) {
        float e = expf(row[c] - mx);
        row[c] = e;
        sum += e;
    }
    sum = blockReduceSum(sum);
    float inv = 1.f / sum;
    for (int c = threadIdx.x; c <= r; c += 256) row[c] *= inv;
    for (int c = r + 1 + threadIdx.x; c < S; c += 256) row[c] = 0.f;
}

__global__ void gate_topk(const float* __restrict__ h2, const float* __restrict__ gw) {
    int n = blockIdx.x;
    int warp = threadIdx.x >> 5, lane = threadIdx.x & 31;
    __shared__ float lg[E];
    const float* x = h2 + (long)n * H;
    const float* w = gw + (long)warp * H;
    float p = 0.f;
    for (int i = lane; i < H; i += 32) p += x[i] * w[i];
    for (int o = 16; o; o >>= 1) p += __shfl_xor_sync(0xffffffffu, p, o);
    if (lane == 0) lg[warp] = p;
    __syncthreads();
    if (threadIdx.x == 0) {
        float mx = lg[0];
        for (int e = 1; e < E; e++) mx = fmaxf(mx, lg[e]);
        float pe[E], s = 0.f;
        for (int e = 0; e < E; e++) { pe[e] = expf(lg[e] - mx); s += pe[e]; }
        float inv = 1.f / s;
        for (int e = 0; e < E; e++) pe[e] *= inv;
        int i1 = 0;
        for (int e = 1; e < E; e++) if (pe[e] > pe[i1]) i1 = e;
        int i2 = (i1 == 0) ? 1 : 0;
        for (int e = 0; e < E; e++) if (e != i1 && pe[e] > pe[i2]) i2 = e;
        float w1 = pe[i1], w2 = pe[i2];
        float wi = 1.f / (w1 + w2 + 1e-20f);
        w1 *= wi; w2 *= wi;
        int s1 = atomicAdd(&g_counts[i1], 1);
        g_tok[i1 * S + s1] = n; g_tw[i1 * S + s1] = w1; g_rank[i1 * S + s1] = 0;
        int s2 = atomicAdd(&g_counts[i2], 1);
        g_tok[i2 * S + s2] = n; g_tw[i2 * S + s2] = w2; g_rank[i2 * S + s2] = 1;
    }
}

__global__ void silu_expert() {
    int e = blockIdx.y;
    long total = (long)g_counts[e] * FI;
    float* gb = g_eg + (long)e * S * FI;
    const float* ub = g_eu + (long)e * S * FI;
    for (long i = (long)blockIdx.x * blockDim.x + threadIdx.x; i < total;
         i += (long)gridDim.x * blockDim.x) {
        float gv = gb[i];
        gb[i] = gv / (1.f + expf(-gv)) * ub[i];
    }
}

__global__ void silu_shared() {
    long total = (long)S * SFI;
    for (long i = (long)blockIdx.x * blockDim.x + threadIdx.x; i < total;
         i += (long)gridDim.x * blockDim.x) {
        float gv = g_sg[i];
        g_sg[i] = gv / (1.f + expf(-gv)) * g_su[i];
    }
}

__global__ void final_add(float* __restrict__ out) {
    long i = (long)blockIdx.x * blockDim.x + threadIdx.x;
    out[i] = g_x[i] + g_routed[i] + g_routed[(long)S * H + i] + g_sd[i];
}

// ---------------- launch ----------------
extern "C" void kernel_launch(void* const* d_in, const int* in_sizes, int n_in,
                              void* d_out, int out_size) {
    const float* hs  = (const float*)d_in[0];
    const float* ln1 = (const float*)d_in[1];
    const float* ln2 = (const float*)d_in[2];
    const float* wq  = (const float*)d_in[3];
    const float* wk  = (const float*)d_in[4];
    const float* wv  = (const float*)d_in[5];
    const float* wo  = (const float*)d_in[6];
    const float* gw  = (const float*)d_in[7];
    const float* eg  = (const float*)d_in[8];
    const float* eu  = (const float*)d_in[9];
    const float* ed  = (const float*)d_in[10];
    const float* sgw = (const float*)d_in[11];
    const float* suw = (const float*)d_in[12];
    const float* sdw = (const float*)d_in[13];
    float* out = (float*)d_out;

    cudaFuncSetAttribute(gemm_tf32, cudaFuncAttributeMaxDynamicSharedMemorySize,
                         DYN_SMEM_BYTES);

    float *p_h1, *p_q, *p_k, *p_vt, *p_scores, *p_attn, *p_x, *p_h2;
    float *p_eg, *p_eu, *p_routed, *p_sg, *p_su, *p_sd, *p_tw;
    int *p_counts, *p_tok, *p_rank;
    cudaGetSymbolAddress((void**)&p_h1, g_h1);
    cudaGetSymbolAddress((void**)&p_q, g_q);
    cudaGetSymbolAddress((void**)&p_k, g_k);
    cudaGetSymbolAddress((void**)&p_vt, g_vt);
    cudaGetSymbolAddress((void**)&p_scores, g_scores);
    cudaGetSymbolAddress((void**)&p_attn, g_attn);
    cudaGetSymbolAddress((void**)&p_x, g_x);
    cudaGetSymbolAddress((void**)&p_h2, g_h2);
    cudaGetSymbolAddress((void**)&p_eg, g_eg);
    cudaGetSymbolAddress((void**)&p_eu, g_eu);
    cudaGetSymbolAddress((void**)&p_routed, g_routed);
    cudaGetSymbolAddress((void**)&p_sg, g_sg);
    cudaGetSymbolAddress((void**)&p_su, g_su);
    cudaGetSymbolAddress((void**)&p_sd, g_sd);
    cudaGetSymbolAddress((void**)&p_tw, g_tw);
    cudaGetSymbolAddress((void**)&p_counts, g_counts);
    cudaGetSymbolAddress((void**)&p_tok, g_tok);
    cudaGetSymbolAddress((void**)&p_rank, g_rank);

    init_misc<<<1, 64>>>();
    rmsnorm_kernel<<<S, 256>>>(hs, ln1, p_h1);

    dim3 gqkv(16, 8, 1);
    gemm_tf32<<<gqkv, 256, DYN_SMEM_BYTES>>>(p_h1, H, 0, wq, H, 0, p_q, H, 0, S, H, H, 1.f,
                             nullptr, nullptr, nullptr, nullptr, nullptr, nullptr, 0, 0);
    gemm_tf32<<<gqkv, 256, DYN_SMEM_BYTES>>>(p_h1, H, 0, wk, H, 0, p_k, H, 0, S, H, H, 1.f,
                             nullptr, nullptr, nullptr, nullptr, nullptr, nullptr, 0, 0);
    // V projection with transposed store -> g_vt[H][S]
    gemm_tf32<<<gqkv, 256, DYN_SMEM_BYTES>>>(p_h1, H, 0, wv, H, 0, p_vt, S, 0, S, H, H, 1.f,
                             nullptr, nullptr, nullptr, nullptr, nullptr, nullptr, 0, 8);

    rope_kernel<<<S, 256>>>();

    // scores = Q K^T / sqrt(HD), causal tile skip
    dim3 gsc(8, 8, NH);
    gemm_tf32<<<gsc, 256, DYN_SMEM_BYTES>>>(p_q, H, (long)HD, p_k, H, (long)HD,
                            p_scores, S, (long)S * S, S, S, HD, 0.08838834764831845f,
                            nullptr, nullptr, nullptr, nullptr, nullptr, nullptr, 0, 4);

    dim3 gsm(S, NH);
    softmax_causal<<<gsm, 256>>>(p_scores);

    // attn = P @ V  (V transposed -> K-major B)
    dim3 gpv(1, 8, NH);
    gemm_tf32<<<gpv, 256, DYN_SMEM_BYTES>>>(p_scores, S, (long)S * S, p_vt, S, (long)HD * S,
                            p_attn, H, (long)HD, S, HD, S, 1.f,
                            nullptr, nullptr, nullptr, nullptr, nullptr, nullptr, 0, 0);

    // x = residual + attn @ wo^T
    gemm_tf32<<<gqkv, 256, DYN_SMEM_BYTES>>>(p_attn, H, 0, wo, H, 0, p_x, H, 0, S, H, H, 1.f,
                             hs, nullptr, nullptr, nullptr, nullptr, nullptr, 0, 0);

    rmsnorm_kernel<<<S, 256>>>(p_x, ln2, p_h2);
    gate_topk<<<S, 256>>>(p_h2, gw);

    // routed experts (sparse, capacity grid with early exit on counts)
    dim3 geg(11, 8, E);
    gemm_tf32<<<geg, 256, DYN_SMEM_BYTES>>>(p_h2, H, 0, eg, H, (long)FI * H, p_eg, FI, (long)S * FI,
                            S, FI, H, 1.f, nullptr, p_counts, p_tok, nullptr, nullptr,
                            nullptr, 0, 1);
    gemm_tf32<<<geg, 256, DYN_SMEM_BYTES>>>(p_h2, H, 0, eu, H, (long)FI * H, p_eu, FI, (long)S * FI,
                            S, FI, H, 1.f, nullptr, p_counts, p_tok, nullptr, nullptr,
                            nullptr, 0, 1);
    silu_expert<<<dim3(768, E), 256>>>();
    dim3 ged(16, 8, E);
    gemm_tf32<<<ged, 256, DYN_SMEM_BYTES>>>(p_eg, FI, (long)S * FI, ed, FI, (long)H * FI,
                            p_routed, H, 0, S, H, FI, 1.f,
                            nullptr, p_counts, p_tok, p_tw, p_rank,
                            p_routed, (long)S * H, 2);

    // shared expert
    dim3 gsg(22, 8, 1);
    gemm_tf32<<<gsg, 256, DYN_SMEM_BYTES>>>(p_h2, H, 0, sgw, H, 0, p_sg, SFI, 0, S, SFI, H, 1.f,
                            nullptr, nullptr, nullptr, nullptr, nullptr, nullptr, 0, 0);
    gemm_tf32<<<gsg, 256, DYN_SMEM_BYTES>>>(p_h2, H, 0, suw, H, 0, p_su, SFI, 0, S, SFI, H, 1.f,
                            nullptr, nullptr, nullptr, nullptr, nullptr, nullptr, 0, 0);
    silu_shared<<<1024, 256>>>();
    dim3 gsd(16, 8, 1);
    gemm_tf32<<<gsd, 256, DYN_SMEM_BYTES>>>(p_sg, SFI, 0, sdw, SFI, 0, p_sd, H, 0, S, H, SFI, 1.f,
                            nullptr, nullptr, nullptr, nullptr, nullptr, nullptr, 0, 0);

    final_add<<<(S * H) / 256, 256>>>(out);
}

// round 16
// speedup vs baseline: 1.4940x; 1.1297x over previous
#include <cuda_runtime.h>
#include <cuda.h>
#include <cuda_bf16.h>
#include <math.h>

#define S 1024
#define H 2048
#define NH 16
#define HD 128
#define E 8
#define FI 1408
#define SFI 2816

#define ST 4
#define CHUNK 32
#define STAGE_A 16384
#define STAGE_BYTES 32768
#define DYN_BYTES (ST * STAGE_BYTES + 1024)
#define NTHREADS 288   // 8 compute warps + producer warp

// ---------------- scratch (device globals: allocation-free) ----------------
__device__ float g_h1[S * H];
__device__ float g_q[S * H];
__device__ float g_k[S * H];
__device__ float g_vt[H * S];            // transposed V: [H][S]
__device__ float g_scores[(size_t)NH * S * S];
__device__ float g_attn[S * H];
__device__ float g_x[S * H];
__device__ float g_h2[S * H];
__device__ float g_gath[(size_t)E * S * H];   // gathered tokens per expert
__device__ float g_eg[(size_t)E * S * FI];
__device__ float g_eu[(size_t)E * S * FI];
__device__ float g_routed[2ul * S * H];  // two top-k rank slots
__device__ float g_sg[(size_t)S * SFI];
__device__ float g_su[(size_t)S * SFI];
__device__ float g_sd[S * H];
__device__ int   g_counts[E];
__device__ int   g_tok[E * S];
__device__ float g_tw[E * S];
__device__ int   g_rank[E * S];
__device__ float g_invfreq[64];

// ---------------- device helpers ----------------
__device__ __forceinline__ unsigned smem_u32(const void* p) {
    unsigned a;
    asm("{ .reg .u64 t; cvta.to.shared.u64 t, %1; cvt.u32.u64 %0, t; }" : "=r"(a) : "l"(p));
    return a;
}

#define MBAR_INIT(addr, cnt) \
    asm volatile("mbarrier.init.shared.b64 [%0], %1;" :: "r"(addr), "r"(cnt) : "memory")
#define MBAR_EXPECT(addr, tx) \
    asm volatile("mbarrier.arrive.expect_tx.shared.b64 _, [%0], %1;" :: "r"(addr), "r"(tx) : "memory")
#define MBAR_ARRIVE(addr) \
    asm volatile("mbarrier.arrive.shared.b64 _, [%0];" :: "r"(addr) : "memory")
#define MBAR_INVAL(addr) \
    asm volatile("mbarrier.inval.shared.b64 [%0];" :: "r"(addr) : "memory")

// relaxed wait: producer side (post-wait accesses are async-proxy TMA)
#define MBAR_WAIT_RLX(addr, ph) do {                                               \
    asm volatile(                                                                  \
        "{\n\t.reg .pred P1;\n\t"                                                  \
        "WL_%=:\n\t"                                                               \
        "mbarrier.try_wait.parity.relaxed.cta.shared::cta.b64 P1, [%0], %1, 0x989680;\n\t" \
        "@P1 bra.uni WD_%=;\n\t"                                                   \
        "bra.uni WL_%=;\n\t"                                                       \
        "WD_%=:\n\t}"                                                              \
        :: "r"(addr), "r"(ph) : "memory");                                         \
} while (0)

// acquire wait: consumer side (generic ld.shared follows)
#define MBAR_WAIT_ACQ(addr, ph) do {                                               \
    asm volatile(                                                                  \
        "{\n\t.reg .pred P1;\n\t"                                                  \
        "WL_%=:\n\t"                                                               \
        "mbarrier.try_wait.parity.acquire.cta.shared::cta.b64 P1, [%0], %1, 0x989680;\n\t" \
        "@P1 bra.uni WD_%=;\n\t"                                                   \
        "bra.uni WL_%=;\n\t"                                                       \
        "WD_%=:\n\t}"                                                              \
        :: "r"(addr), "r"(ph) : "memory");                                         \
} while (0)

#define TMA2D(sa, tmp, cx, cy, mb)                                                 \
    asm volatile(                                                                  \
        "cp.async.bulk.tensor.2d.shared::cta.global.tile.mbarrier::complete_tx::bytes " \
        "[%0], [%1, {%2, %3}], [%4];"                                              \
        :: "r"(sa), "l"(tmp), "r"(cx), "r"(cy), "r"(mb) : "memory")

__device__ __forceinline__ unsigned ld_tf32(float v) {
    float r;
    asm("cvt.rna.tf32.f32 %0, %1;" : "=f"(r) : "f"(v));
    return __float_as_uint(r);
}

// swizzle-aware SMEM read: TMA SW128 stores logical (row, col<32 floats) at
// float index row*32 + (col ^ ((row&7)<<2))
__device__ __forceinline__ float lds_sw(const float* tile, int row, int col) {
    return tile[row * 32 + (col ^ ((row & 7) << 2))];
}

__device__ __forceinline__ float blockReduceSum(float v) {
    __shared__ float sm[8];
    for (int o = 16; o; o >>= 1) v += __shfl_xor_sync(0xffffffffu, v, o);
    if ((threadIdx.x & 31) == 0) sm[threadIdx.x >> 5] = v;
    __syncthreads();
    float r = sm[0];
#pragma unroll
    for (int i = 1; i < 8; i++) r += sm[i];
    __syncthreads();
    return r;
}

__device__ __forceinline__ float blockReduceMax(float v) {
    __shared__ float sm[8];
    for (int o = 16; o; o >>= 1) v = fmaxf(v, __shfl_xor_sync(0xffffffffu, v, o));
    if ((threadIdx.x & 31) == 0) sm[threadIdx.x >> 5] = v;
    __syncthreads();
    float r = sm[0];
#pragma unroll
    for (int i = 1; i < 8; i++) r = fmaxf(r, sm[i]);
    __syncthreads();
    return r;
}

// ---------------- TMA + mma.sync tf32 GEMM: C[M,N] = scale * A[M,K] * B[N,K]^T ------
// flags: 2 = scatter epilogue (routed MoE), 4 = causal tile skip, 8 = transposed C store
__global__ void __launch_bounds__(NTHREADS, 1) gemm_tma(
    const __grid_constant__ CUtensorMap tA,
    const __grid_constant__ CUtensorMap tB,
    int aXz, int aYz, int bXz, int bYz,
    float* __restrict__ C, int ldc, long sCz,
    int M, int N, int K, float scale,
    const float* __restrict__ addsrc,
    const int* __restrict__ counts,
    const int* __restrict__ tok,
    const float* __restrict__ tw,
    const int* __restrict__ rnk,
    float* __restrict__ scat, long scatStride,
    int flags)
{
    const int z  = blockIdx.z;
    const int m0 = blockIdx.y * 128;
    const int n0 = blockIdx.x * 128;
    const int Meff = counts ? counts[z] : M;
    if (m0 >= Meff) return;
    if ((flags & 4) && n0 >= m0 + 128) return;

    extern __shared__ char dsm[];
    const unsigned tile0 = (smem_u32(dsm) + 1023u) & ~1023u;
    float* tileBase = (float*)(dsm + (tile0 - smem_u32(dsm)));

    __shared__ __align__(8) unsigned long long s_bar[2 * ST];
    const unsigned barBase = smem_u32(s_bar);

    const int tid = threadIdx.x;

    if (tid == 0) {
#pragma unroll
        for (int s = 0; s < ST; s++) {
            MBAR_INIT(barBase + s * 8, 1);               // full: tx-completed
            MBAR_INIT(barBase + (ST + s) * 8, 256);      // empty: 256 consumers
        }
    }
    __syncthreads();

    const int KT = K / CHUNK;
    const int aX0 = aXz * z, aY0 = aYz * z + m0;
    const int bX0 = bXz * z, bY0 = bYz * z + n0;

    if (tid == 256) {
        // -------- producer (warp 8 lane 0) --------
        const void* pA = (const void*)&tA;
        const void* pB = (const void*)&tB;
        for (int n = 0; n < KT; n++) {
            int s = n % ST;
            if (n >= ST) {
                int m = n / ST;
                MBAR_WAIT_RLX(barBase + (ST + s) * 8, (m - 1) & 1);
            }
            unsigned fb = barBase + s * 8;
            MBAR_EXPECT(fb, STAGE_BYTES);
            TMA2D(tile0 + s * STAGE_BYTES,           pA, aX0 + n * CHUNK, aY0, fb);
            TMA2D(tile0 + s * STAGE_BYTES + STAGE_A, pB, bX0 + n * CHUNK, bY0, fb);
        }
    } else if (tid < 256) {
        // -------- consumers: 8 warps, 64x32 tile each --------
        const int lane = tid & 31, warp = tid >> 5;
        const int wm = (warp >> 2) * 64, wn = (warp & 3) * 32;
        const int g = lane >> 2, t = lane & 3;

        float acc[4][4][4];
#pragma unroll
        for (int a = 0; a < 4; a++)
#pragma unroll
            for (int b = 0; b < 4; b++)
#pragma unroll
                for (int c = 0; c < 4; c++) acc[a][b][c] = 0.f;

        for (int k = 0; k < KT; k++) {
            int s = k % ST;
            MBAR_WAIT_ACQ(barBase + s * 8, (k / ST) & 1);
            const float* cA = tileBase + s * (STAGE_BYTES / 4);
            const float* cB = cA + (STAGE_A / 4);
#pragma unroll
            for (int kk = 0; kk < 32; kk += 8) {
                unsigned af[4][4], bf[4][2];
#pragma unroll
                for (int mi = 0; mi < 4; mi++) {
                    int r = wm + mi * 16;
                    af[mi][0] = ld_tf32(lds_sw(cA, r + g,     kk + t));
                    af[mi][1] = ld_tf32(lds_sw(cA, r + g + 8, kk + t));
                    af[mi][2] = ld_tf32(lds_sw(cA, r + g,     kk + t + 4));
                    af[mi][3] = ld_tf32(lds_sw(cA, r + g + 8, kk + t + 4));
                }
#pragma unroll
                for (int ni = 0; ni < 4; ni++) {
                    int c = wn + ni * 8;
                    bf[ni][0] = ld_tf32(lds_sw(cB, c + g, kk + t));
                    bf[ni][1] = ld_tf32(lds_sw(cB, c + g, kk + t + 4));
                }
#pragma unroll
                for (int mi = 0; mi < 4; mi++)
#pragma unroll
                    for (int ni = 0; ni < 4; ni++)
                        asm volatile(
                            "mma.sync.aligned.m16n8k8.row.col.f32.tf32.tf32.f32 "
                            "{%0,%1,%2,%3}, {%4,%5,%6,%7}, {%8,%9}, {%0,%1,%2,%3};"
                            : "+f"(acc[mi][ni][0]), "+f"(acc[mi][ni][1]),
                              "+f"(acc[mi][ni][2]), "+f"(acc[mi][ni][3])
                            : "r"(af[mi][0]), "r"(af[mi][1]), "r"(af[mi][2]), "r"(af[mi][3]),
                              "r"(bf[ni][0]), "r"(bf[ni][1]));
            }
            MBAR_ARRIVE(barBase + (ST + s) * 8);
        }

        // epilogue: c0=(g,2t) c1=(g,2t+1) c2=(g+8,2t) c3=(g+8,2t+1)
#pragma unroll
        for (int mi = 0; mi < 4; mi++) {
#pragma unroll
            for (int ni = 0; ni < 4; ni++) {
                int r0 = m0 + wm + mi * 16 + g;
                int c0 = n0 + wn + ni * 8 + t * 2;
#pragma unroll
                for (int hh = 0; hh < 2; hh++) {
                    int r = r0 + hh * 8;
                    if (r >= Meff) continue;
                    float v0 = acc[mi][ni][hh * 2 + 0] * scale;
                    float v1 = acc[mi][ni][hh * 2 + 1] * scale;
                    if (flags & 2) {
                        int rr = tok[z * S + r];
                        float w = tw[z * S + r];
                        float* dst = scat + (long)rnk[z * S + r] * scatStride + (long)rr * ldc + c0;
                        dst[0] = w * v0;
                        dst[1] = w * v1;
                    } else if (flags & 8) {
                        C[sCz * z + (long)c0 * ldc + r] = v0;
                        C[sCz * z + (long)(c0 + 1) * ldc + r] = v1;
                    } else {
                        long o = sCz * z + (long)r * ldc + c0;
                        if (addsrc) { v0 += addsrc[o]; v1 += addsrc[o + 1]; }
                        C[o] = v0;
                        C[o + 1] = v1;
                    }
                }
            }
        }
    }

    __syncthreads();
    if (tid == 0) {
#pragma unroll
        for (int s = 0; s < 2 * ST; s++) MBAR_INVAL(barBase + s * 8);
    }
}

// ---------------- small kernels ----------------
__global__ void init_misc() {
    int i = threadIdx.x;
    if (i < 64) g_invfreq[i] = (float)pow(10000.0, -(double)i / 64.0);
    if (i < E)  g_counts[i] = 0;
}

__global__ void rmsnorm_kernel(const float* __restrict__ x, const float* __restrict__ w,
                               float* __restrict__ o) {
    long r = blockIdx.x;
    const float* xr = x + r * H;
    float s = 0.f;
    for (int i = threadIdx.x; i < H; i += 256) { float v = xr[i]; s += v * v; }
    s = blockReduceSum(s);
    float inv = rsqrtf(s / (float)H + 1e-6f);
    for (int i = threadIdx.x; i < H; i += 256) o[r * H + i] = xr[i] * inv * w[i];
}

__global__ void rope_kernel() {
    int s = blockIdx.x;
    for (int p = threadIdx.x; p < NH * 64; p += blockDim.x) {
        int head = p >> 6, i = p & 63;
        float f = (float)s * g_invfreq[i];
        float sn, cs;
        sincosf(f, &sn, &cs);
        long b = (long)s * H + head * HD;
        float q1 = g_q[b + i], q2 = g_q[b + i + 64];
        g_q[b + i]      = q1 * cs - q2 * sn;
        g_q[b + i + 64] = q2 * cs + q1 * sn;
        float k1 = g_k[b + i], k2 = g_k[b + i + 64];
        g_k[b + i]      = k1 * cs - k2 * sn;
        g_k[b + i + 64] = k2 * cs + k1 * sn;
    }
}

__global__ void softmax_causal(float* __restrict__ sc) {
    int h = blockIdx.y, r = blockIdx.x;
    float* row = sc + ((long)h * S + r) * S;
    float mx = -3.4e38f;
    for (int c = threadIdx.x; c <= r; c += 256) mx = fmaxf(mx, row[c]);
    mx = blockReduceMax(mx);
    float sum = 0.f;
    for (int c = threadIdx.x; c <= r; c += 256) {
        float e = expf(row[c] - mx);
        row[c] = e;
        sum += e;
    }
    sum = blockReduceSum(sum);
    float inv = 1.f / sum;
    for (int c = threadIdx.x; c <= r; c += 256) row[c] *= inv;
    for (int c = r + 1 + threadIdx.x; c < S; c += 256) row[c] = 0.f;
}

__global__ void gate_topk(const float* __restrict__ h2, const float* __restrict__ gw) {
    int n = blockIdx.x;
    int warp = threadIdx.x >> 5, lane = threadIdx.x & 31;
    __shared__ float lg[E];
    const float* x = h2 + (long)n * H;
    const float* w = gw + (long)warp * H;
    float p = 0.f;
    for (int i = lane; i < H; i += 32) p += x[i] * w[i];
    for (int o = 16; o; o >>= 1) p += __shfl_xor_sync(0xffffffffu, p, o);
    if (lane == 0) lg[warp] = p;
    __syncthreads();
    if (threadIdx.x == 0) {
        float mx = lg[0];
        for (int e = 1; e < E; e++) mx = fmaxf(mx, lg[e]);
        float pe[E], s = 0.f;
        for (int e = 0; e < E; e++) { pe[e] = expf(lg[e] - mx); s += pe[e]; }
        float inv = 1.f / s;
        for (int e = 0; e < E; e++) pe[e] *= inv;
        int i1 = 0;
        for (int e = 1; e < E; e++) if (pe[e] > pe[i1]) i1 = e;
        int i2 = (i1 == 0) ? 1 : 0;
        for (int e = 0; e < E; e++) if (e != i1 && pe[e] > pe[i2]) i2 = e;
        float w1 = pe[i1], w2 = pe[i2];
        float wi = 1.f / (w1 + w2 + 1e-20f);
        w1 *= wi; w2 *= wi;
        int s1 = atomicAdd(&g_counts[i1], 1);
        g_tok[i1 * S + s1] = n; g_tw[i1 * S + s1] = w1; g_rank[i1 * S + s1] = 0;
        int s2 = atomicAdd(&g_counts[i2], 1);
        g_tok[i2 * S + s2] = n; g_tw[i2 * S + s2] = w2; g_rank[i2 * S + s2] = 1;
    }
}

__global__ void gather_rows() {
    int e = blockIdx.y, slot = blockIdx.x;
    if (slot >= g_counts[e]) return;
    int t = g_tok[e * S + slot];
    float4* d = (float4*)(g_gath + ((long)e * S + slot) * H);
    const float4* s = (const float4*)(g_h2 + (long)t * H);
    for (int i = threadIdx.x; i < H / 4; i += 256) d[i] = s[i];
}

__global__ void silu_expert() {
    int e = blockIdx.y;
    long total = (long)g_counts[e] * FI;
    float* gb = g_eg + (long)e * S * FI;
    const float* ub = g_eu + (long)e * S * FI;
    for (long i = (long)blockIdx.x * blockDim.x + threadIdx.x; i < total;
         i += (long)gridDim.x * blockDim.x) {
        float gv = gb[i];
        gb[i] = gv / (1.f + expf(-gv)) * ub[i];
    }
}

__global__ void silu_shared() {
    long total = (long)S * SFI;
    for (long i = (long)blockIdx.x * blockDim.x + threadIdx.x; i < total;
         i += (long)gridDim.x * blockDim.x) {
        float gv = g_sg[i];
        g_sg[i] = gv / (1.f + expf(-gv)) * g_su[i];
    }
}

__global__ void final_add(float* __restrict__ out) {
    long i = (long)blockIdx.x * blockDim.x + threadIdx.x;
    out[i] = g_x[i] + g_routed[i] + g_routed[(long)S * H + i] + g_sd[i];
}

// ---------------- host side ----------------
typedef CUresult (*EncodeFn)(CUtensorMap*, CUtensorMapDataType, cuuint32_t, void*,
                             const cuuint64_t*, const cuuint64_t*, const cuuint32_t*,
                             const cuuint32_t*, CUtensorMapInterleave, CUtensorMapSwizzle,
                             CUtensorMapL2promotion, CUtensorMapFloatOOBfill);

static CUtensorMap make2d(EncodeFn enc, const void* base, unsigned long long d0,
                          unsigned long long d1, unsigned long long strideBytes) {
    CUtensorMap m;
    cuuint64_t dims[2] = {d0, d1};
    cuuint64_t strides[1] = {strideBytes};
    cuuint32_t box[2] = {32, 128};
    cuuint32_t es[2] = {1, 1};
    enc(&m, CU_TENSOR_MAP_DATA_TYPE_FLOAT32, 2, (void*)base, dims, strides, box, es,
        CU_TENSOR_MAP_INTERLEAVE_NONE, CU_TENSOR_MAP_SWIZZLE_128B,
        CU_TENSOR_MAP_L2_PROMOTION_L2_128B, CU_TENSOR_MAP_FLOAT_OOB_FILL_NONE);
    return m;
}

extern "C" void kernel_launch(void* const* d_in, const int* in_sizes, int n_in,
                              void* d_out, int out_size) {
    const float* hs  = (const float*)d_in[0];
    const float* ln1 = (const float*)d_in[1];
    const float* ln2 = (const float*)d_in[2];
    const float* wq  = (const float*)d_in[3];
    const float* wk  = (const float*)d_in[4];
    const float* wv  = (const float*)d_in[5];
    const float* wo  = (const float*)d_in[6];
    const float* gw  = (const float*)d_in[7];
    const float* eg  = (const float*)d_in[8];
    const float* eu  = (const float*)d_in[9];
    const float* ed  = (const float*)d_in[10];
    const float* sgw = (const float*)d_in[11];
    const float* suw = (const float*)d_in[12];
    const float* sdw = (const float*)d_in[13];
    float* out = (float*)d_out;

    EncodeFn enc = nullptr;
    cudaDriverEntryPointQueryResult qs;
    cudaGetDriverEntryPoint("cuTensorMapEncodeTiled", (void**)&enc, cudaEnableDefault, &qs);

    cudaFuncSetAttribute(gemm_tma, cudaFuncAttributeMaxDynamicSharedMemorySize, DYN_BYTES);

    float *p_h1, *p_q, *p_k, *p_vt, *p_scores, *p_attn, *p_x, *p_h2, *p_gath;
    float *p_eg, *p_eu, *p_routed, *p_sg, *p_su, *p_sd, *p_tw;
    int *p_counts, *p_tok, *p_rank;
    cudaGetSymbolAddress((void**)&p_h1, g_h1);
    cudaGetSymbolAddress((void**)&p_q, g_q);
    cudaGetSymbolAddress((void**)&p_k, g_k);
    cudaGetSymbolAddress((void**)&p_vt, g_vt);
    cudaGetSymbolAddress((void**)&p_scores, g_scores);
    cudaGetSymbolAddress((void**)&p_attn, g_attn);
    cudaGetSymbolAddress((void**)&p_x, g_x);
    cudaGetSymbolAddress((void**)&p_h2, g_h2);
    cudaGetSymbolAddress((void**)&p_gath, g_gath);
    cudaGetSymbolAddress((void**)&p_eg, g_eg);
    cudaGetSymbolAddress((void**)&p_eu, g_eu);
    cudaGetSymbolAddress((void**)&p_routed, g_routed);
    cudaGetSymbolAddress((void**)&p_sg, g_sg);
    cudaGetSymbolAddress((void**)&p_su, g_su);
    cudaGetSymbolAddress((void**)&p_sd, g_sd);
    cudaGetSymbolAddress((void**)&p_tw, g_tw);
    cudaGetSymbolAddress((void**)&p_counts, g_counts);
    cudaGetSymbolAddress((void**)&p_tok, g_tok);
    cudaGetSymbolAddress((void**)&p_rank, g_rank);

    // tensormaps
    CUtensorMap mH1  = make2d(enc, p_h1, H, S, (unsigned long long)H * 4);
    CUtensorMap mWQ  = make2d(enc, wq,  H, H, (unsigned long long)H * 4);
    CUtensorMap mWK  = make2d(enc, wk,  H, H, (unsigned long long)H * 4);
    CUtensorMap mWV  = make2d(enc, wv,  H, H, (unsigned long long)H * 4);
    CUtensorMap mWO  = make2d(enc, wo,  H, H, (unsigned long long)H * 4);
    CUtensorMap mQ   = make2d(enc, p_q, H, S, (unsigned long long)H * 4);
    CUtensorMap mK   = make2d(enc, p_k, H, S, (unsigned long long)H * 4);
    CUtensorMap mP   = make2d(enc, p_scores, S, (unsigned long long)NH * S, (unsigned long long)S * 4);
    CUtensorMap mVT  = make2d(enc, p_vt, S, H, (unsigned long long)S * 4);
    CUtensorMap mAT  = make2d(enc, p_attn, H, S, (unsigned long long)H * 4);
    CUtensorMap mH2  = make2d(enc, p_h2, H, S, (unsigned long long)H * 4);
    CUtensorMap mGA  = make2d(enc, p_gath, H, (unsigned long long)E * S, (unsigned long long)H * 4);
    CUtensorMap mEG  = make2d(enc, eg, H, (unsigned long long)E * FI, (unsigned long long)H * 4);
    CUtensorMap mEU  = make2d(enc, eu, H, (unsigned long long)E * FI, (unsigned long long)H * 4);
    CUtensorMap mACT = make2d(enc, p_eg, FI, (unsigned long long)E * S, (unsigned long long)FI * 4);
    CUtensorMap mED  = make2d(enc, ed, FI, (unsigned long long)E * H, (unsigned long long)FI * 4);
    CUtensorMap mSG  = make2d(enc, sgw, H, SFI, (unsigned long long)H * 4);
    CUtensorMap mSU  = make2d(enc, suw, H, SFI, (unsigned long long)H * 4);
    CUtensorMap mSA  = make2d(enc, p_sg, SFI, S, (unsigned long long)SFI * 4);
    CUtensorMap mSD  = make2d(enc, sdw, SFI, H, (unsigned long long)SFI * 4);

    init_misc<<<1, 64>>>();
    rmsnorm_kernel<<<S, 256>>>(hs, ln1, p_h1);

    dim3 gqkv(16, 8, 1);
    gemm_tma<<<gqkv, NTHREADS, DYN_BYTES>>>(mH1, mWQ, 0, 0, 0, 0, p_q, H, 0, S, H, H, 1.f,
                                    nullptr, nullptr, nullptr, nullptr, nullptr, nullptr, 0, 0);
    gemm_tma<<<gqkv, NTHREADS, DYN_BYTES>>>(mH1, mWK, 0, 0, 0, 0, p_k, H, 0, S, H, H, 1.f,
                                    nullptr, nullptr, nullptr, nullptr, nullptr, nullptr, 0, 0);
    gemm_tma<<<gqkv, NTHREADS, DYN_BYTES>>>(mH1, mWV, 0, 0, 0, 0, p_vt, S, 0, S, H, H, 1.f,
                                    nullptr, nullptr, nullptr, nullptr, nullptr, nullptr, 0, 8);

    rope_kernel<<<S, 256>>>();

    // scores = Q K^T / sqrt(HD): A = q (x offset HD per head), B = k
    dim3 gsc(8, 8, NH);
    gemm_tma<<<gsc, NTHREADS, DYN_BYTES>>>(mQ, mK, HD, 0, HD, 0,
                                   p_scores, S, (long)S * S, S, S, HD, 0.08838834764831845f,
                                   nullptr, nullptr, nullptr, nullptr, nullptr, nullptr, 0, 4);

    dim3 gsm(S, NH);
    softmax_causal<<<gsm, 256>>>(p_scores);

    // attn = P @ V  (A = P rows per head, B = vt rows per head)
    dim3 gpv(1, 8, NH);
    gemm_tma<<<gpv, NTHREADS, DYN_BYTES>>>(mP, mVT, 0, S, 0, HD,
                                   p_attn, H, (long)HD, S, HD, S, 1.f,
                                   nullptr, nullptr, nullptr, nullptr, nullptr, nullptr, 0, 0);

    // x = residual + attn @ wo^T
    gemm_tma<<<gqkv, NTHREADS, DYN_BYTES>>>(mAT, mWO, 0, 0, 0, 0, p_x, H, 0, S, H, H, 1.f,
                                    hs, nullptr, nullptr, nullptr, nullptr, nullptr, 0, 0);

    rmsnorm_kernel<<<S, 256>>>(p_x, ln2, p_h2);
    gate_topk<<<S, 256>>>(p_h2, gw);
    gather_rows<<<dim3(S, E), 256>>>();

    // routed experts
    dim3 geg(11, 8, E);
    gemm_tma<<<geg, NTHREADS, DYN_BYTES>>>(mGA, mEG, 0, S, 0, FI,
                                   p_eg, FI, (long)S * FI, S, FI, H, 1.f,
                                   nullptr, p_counts, nullptr, nullptr, nullptr, nullptr, 0, 0);
    gemm_tma<<<geg, NTHREADS, DYN_BYTES>>>(mGA, mEU, 0, S, 0, FI,
                                   p_eu, FI, (long)S * FI, S, FI, H, 1.f,
                                   nullptr, p_counts, nullptr, nullptr, nullptr, nullptr, 0, 0);
    silu_expert<<<dim3(768, E), 256>>>();
    dim3 ged(16, 8, E);
    gemm_tma<<<ged, NTHREADS, DYN_BYTES>>>(mACT, mED, 0, S, 0, H,
                                   p_routed, H, 0, S, H, FI, 1.f,
                                   nullptr, p_counts, p_tok, p_tw, p_rank,
                                   p_routed, (long)S * H, 2);

    // shared expert
    dim3 gsg(22, 8, 1);
    gemm_tma<<<gsg, NTHREADS, DYN_BYTES>>>(mH2, mSG, 0, 0, 0, 0, p_sg, SFI, 0, S, SFI, H, 1.f,
                                   nullptr, nullptr, nullptr, nullptr, nullptr, nullptr, 0, 0);
    gemm_tma<<<gsg, NTHREADS, DYN_BYTES>>>(mH2, mSU, 0, 0, 0, 0, p_su, SFI, 0, S, SFI, H, 1.f,
                                   nullptr, nullptr, nullptr, nullptr, nullptr, nullptr, 0, 0);
    silu_shared<<<1024, 256>>>();
    dim3 gsd(16, 8, 1);
    gemm_tma<<<gsd, NTHREADS, DYN_BYTES>>>(mSA, mSD, 0, 0, 0, 0, p_sd, H, 0, S, H, SFI, 1.f,
                                   nullptr, nullptr, nullptr, nullptr, nullptr, nullptr, 0, 0);

    final_add<<<(S * H) / 256, 256>>>(out);
}